// round 5
// baseline (speedup 1.0000x reference)
#include <cuda_runtime.h>
#include <cuda_bf16.h>
#include <math.h>

// Shapes (fixed by the problem)
#define NQ   10
#define NL   4
#define NG   (NL * NQ)
#define NDIM 1024
#define FFN  4096
#define EDIM 1024
#define NTOK 16384
#define GRID 65          // blocks 0..63 = compute+fill (16 cols each), 64 = circuit

// Persistent state. g_entry/g_zflag are monotonic across graph replays: no reset.
__device__ int g_entry = 0;
__device__ int g_zflag = 0;
__device__ float g_z[16];

__device__ __forceinline__ float2 cmul(float2 a, float2 b) {
    return make_float2(fmaf(a.x, b.x, -a.y * b.y), fmaf(a.x, b.y, a.y * b.x));
}
__device__ __forceinline__ float2 cfma2(float2 u, float2 a, float2 v, float2 b) {
    float re = fmaf(u.x, a.x, -u.y * a.y);
    re = fmaf(v.x, b.x, re);
    re = fmaf(-v.y, b.y, re);
    float im = fmaf(u.x, a.y, u.y * a.x);
    im = fmaf(v.x, b.y, im);
    im = fmaf(v.y, b.x, im);
    return make_float2(re, im);
}
__device__ __forceinline__ void l2_prefetch(const void* p) {
    asm volatile("prefetch.global.L2 [%0];" :: "l"(p));
}

#define SIDX(i) ((i) + ((i) >> 5))

__global__ void __launch_bounds__(1024, 1)
fused_kernel(const float* __restrict__ params,
             const float* __restrict__ W1,
             const float* __restrict__ b1,
             const float* __restrict__ W2,
             const float* __restrict__ b2,
             float* __restrict__ out) {
    __shared__ float2 U[NG][2];
    __shared__ float2 st[2][NDIM + 32];
    __shared__ float  wsum[32][NQ];
    __shared__ float  h_s[FFN];
    __shared__ float  y_s[16];
    __shared__ float  red2[16][2];
    __shared__ int    s_epoch;

    const int t    = threadIdx.x;
    const int b    = blockIdx.x;
    const int lane = t & 31;
    const int warp = t >> 5;

    if (t == 0) s_epoch = atomicAdd(&g_entry, 1) / GRID;
    __syncthreads();
    const int target = s_epoch + 1;

    if (b == 64) {
        // ===================== circuit block =====================
        if (t < NG) {
            const float t0 = params[t * 3 + 0];
            const float t1 = params[t * 3 + 1];
            const float t2 = params[t * 3 + 2];
            float cx, sx, cy, sy, cz, sz;
            sincosf(0.5f * t0, &sx, &cx);
            sincosf(0.5f * t1, &sy, &cy);
            sincosf(0.5f * t2, &sz, &cz);
            const float2 m00 = make_float2( cy * cx,  sy * sx);
            const float2 m01 = make_float2(-sy * cx, -cy * sx);
            const float2 ezm = make_float2(cz, -sz);
            U[t][0] = cmul(ezm, m00);
            U[t][1] = cmul(ezm, m01);
        }
        const int Pt = ((t & 31) << 5) | (t >> 5);
        int Ct = t;
        #pragma unroll
        for (int e = NQ - 1; e >= 0; e--) {
            const int c  = (e < NQ - 1) ? e : NQ - 1;
            const int tq = (e < NQ - 1) ? e + 1 : 0;
            const int cm = 1 << (NQ - 1 - c);
            const int tm = 1 << (NQ - 1 - tq);
            Ct ^= (Ct & cm) ? tm : 0;
        }
        float sgn[5];
        #pragma unroll
        for (int k = 0; k < 5; k++) sgn[k] = (t & (16 >> k)) ? -1.0f : 1.0f;

        float2 a = make_float2(t == 0 ? 1.0f : 0.0f, 0.0f);
        __syncthreads();

        int cur = 0;
        #pragma unroll 1
        for (int l = 0; l < NL; l++) {
            #pragma unroll
            for (int k = 0; k < 5; k++) {
                const int g = l * NQ + 5 + k;
                float2 u0 = U[g][0];
                float2 u1 = U[g][1];
                const float s = sgn[k];
                u0.y *= s; u1.x *= s;
                const int m = 16 >> k;
                float2 bb;
                bb.x = __shfl_xor_sync(0xffffffffu, a.x, m);
                bb.y = __shfl_xor_sync(0xffffffffu, a.y, m);
                a = cfma2(u0, a, u1, bb);
            }
            st[cur][SIDX(t)] = a;
            __syncthreads();
            a = st[cur][SIDX(Pt)];
            cur ^= 1;
            #pragma unroll
            for (int k = 0; k < 5; k++) {
                const int g = l * NQ + k;
                float2 u0 = U[g][0];
                float2 u1 = U[g][1];
                const float s = sgn[k];
                u0.y *= s; u1.x *= s;
                const int m = 16 >> k;
                float2 bb;
                bb.x = __shfl_xor_sync(0xffffffffu, a.x, m);
                bb.y = __shfl_xor_sync(0xffffffffu, a.y, m);
                a = cfma2(u0, a, u1, bb);
            }
            st[cur][SIDX(Pt)] = a;
            __syncthreads();
            a = st[cur][SIDX(Ct)];
            cur ^= 1;
        }

        const float p = fmaf(a.x, a.x, a.y * a.y);
        #pragma unroll
        for (int q = 0; q < NQ; q++) {
            const int mask = 1 << (NQ - 1 - q);
            float v = (t & mask) ? p : 0.0f;
            #pragma unroll
            for (int o = 16; o > 0; o >>= 1) v += __shfl_xor_sync(0xffffffffu, v, o);
            if (lane == 0) wsum[warp][q] = v;
        }
        __syncthreads();
        if (t < NQ) {
            float s = 0.0f;
            #pragma unroll
            for (int w = 0; w < 32; w++) s += wsum[w][t];
            g_z[t] = 1.0f - 2.0f * s;
        }
        __syncthreads();
        if (t == 0) {
            __threadfence();
            atomicMax(&g_zflag, target);   // release, monotonic (no reset needed)
        }
        return;
    }

    // ===================== compute + fill blocks (0..63) =====================
    // prefetch own W2 slice (16 rows x 16KB = 256KB = 2048 lines) into L2
    {
        const char* w2b = (const char*)(W2 + (size_t)b * 16 * FFN);
        l2_prefetch(w2b + (size_t)t * 128);
        l2_prefetch(w2b + (size_t)(t + 1024) * 128);
        if (b == 0 && t < 640) l2_prefetch((const char*)W1 + (size_t)t * 128);
        if (b == 1 && t < 640) l2_prefetch((const char*)W1 + (size_t)(640 + t) * 128);
        if (b == 2 && t < 128) l2_prefetch((const char*)b1 + (size_t)t * 128);
        if (b == 3 && t < 32)  l2_prefetch((const char*)b2 + (size_t)t * 128);
    }

    // wait for z (single flag, acquire)
    if (t == 0) {
        while (((volatile int*)&g_zflag)[0] < target) __nanosleep(32);
    }
    __syncthreads();
    __threadfence();

    float z[NQ];
    #pragma unroll
    for (int q = 0; q < NQ; q++) z[q] = g_z[q];

    // h = relu(W1 z + b1) (redundant per block; W1 is L2-warm). thread t -> rows 4t..4t+3
    {
        const float4* __restrict__ Wv = ((const float4*)W1) + (size_t)t * 10;
        float f[20];
        float acc[4];

        float4 v0 = Wv[0], v1 = Wv[1], v2 = Wv[2], v3 = Wv[3], v4 = Wv[4];
        f[0]=v0.x; f[1]=v0.y; f[2]=v0.z; f[3]=v0.w;
        f[4]=v1.x; f[5]=v1.y; f[6]=v1.z; f[7]=v1.w;
        f[8]=v2.x; f[9]=v2.y; f[10]=v2.z; f[11]=v2.w;
        f[12]=v3.x; f[13]=v3.y; f[14]=v3.z; f[15]=v3.w;
        f[16]=v4.x; f[17]=v4.y; f[18]=v4.z; f[19]=v4.w;
        acc[0] = 0.0f; acc[1] = 0.0f;
        #pragma unroll
        for (int q = 0; q < NQ; q++) acc[0] = fmaf(f[q],      z[q], acc[0]);
        #pragma unroll
        for (int q = 0; q < NQ; q++) acc[1] = fmaf(f[10 + q], z[q], acc[1]);

        v0 = Wv[5]; v1 = Wv[6]; v2 = Wv[7]; v3 = Wv[8]; v4 = Wv[9];
        f[0]=v0.x; f[1]=v0.y; f[2]=v0.z; f[3]=v0.w;
        f[4]=v1.x; f[5]=v1.y; f[6]=v1.z; f[7]=v1.w;
        f[8]=v2.x; f[9]=v2.y; f[10]=v2.z; f[11]=v2.w;
        f[12]=v3.x; f[13]=v3.y; f[14]=v3.z; f[15]=v3.w;
        f[16]=v4.x; f[17]=v4.y; f[18]=v4.z; f[19]=v4.w;
        acc[2] = 0.0f; acc[3] = 0.0f;
        #pragma unroll
        for (int q = 0; q < NQ; q++) acc[2] = fmaf(f[q],      z[q], acc[2]);
        #pragma unroll
        for (int q = 0; q < NQ; q++) acc[3] = fmaf(f[10 + q], z[q], acc[3]);

        const float4 bb = ((const float4*)b1)[t];
        float4 hv;
        hv.x = fmaxf(acc[0] + bb.x, 0.0f);
        hv.y = fmaxf(acc[1] + bb.y, 0.0f);
        hv.z = fmaxf(acc[2] + bb.z, 0.0f);
        hv.w = fmaxf(acc[3] + bb.w, 0.0f);
        ((float4*)h_s)[t] = hv;
    }
    __syncthreads();

    // y slice: outputs e = 16b + g, g = t>>6 (two warps per output)
    {
        const int g = t >> 6;
        const int j = t & 63;
        const float4* __restrict__ w4 = (const float4*)(W2 + (size_t)(b * 16 + g) * FFN);
        const float4* __restrict__ h4 = (const float4*)h_s;
        float acc = 0.0f;
        #pragma unroll
        for (int k = 0; k < 16; k++) {
            const int idx = j + 64 * k;
            const float4 w = w4[idx];
            const float4 h = h4[idx];
            acc += w.x * h.x + w.y * h.y + w.z * h.z + w.w * h.w;
        }
        #pragma unroll
        for (int o = 16; o > 0; o >>= 1) acc += __shfl_down_sync(0xffffffffu, acc, o);
        if (lane == 0) red2[g][(t >> 5) & 1] = acc;
        __syncthreads();
        if (t < 16) y_s[t] = red2[t][0] + red2[t][1] + b2[b * 16 + t];
        __syncthreads();
    }

    // fill: block b writes cols [16b,16b+16) of every row. 64B/row segments.
    {
        const int cg = t & 3;                 // which float4 of the 64B segment
        const int rs = t >> 2;                // 0..255 row stream
        const float4 v = ((const float4*)y_s)[cg];
        float4* __restrict__ o4 = (float4*)out + (size_t)b * 4 + cg;
        #pragma unroll 8
        for (int i = 0; i < 64; i++) {
            const int r = rs + 256 * i;
            o4[(size_t)r * 256] = v;
        }
    }
}

// ---------------------------------------------------------------------------
// inputs: 0=x, 1=W_in, 2=b_in, 3=params, 4=W1, 5=b1, 6=W2, 7=b2
// x / W_in / b_in are dead in the reference.
// ---------------------------------------------------------------------------
extern "C" void kernel_launch(void* const* d_in, const int* in_sizes, int n_in,
                              void* d_out, int out_size) {
    const float* params = (const float*)d_in[3];
    const float* W1     = (const float*)d_in[4];
    const float* b1     = (const float*)d_in[5];
    const float* W2     = (const float*)d_in[6];
    const float* b2     = (const float*)d_in[7];
    float* out = (float*)d_out;

    fused_kernel<<<GRID, 1024>>>(params, W1, b1, W2, b2, out);
}

// round 6
// speedup vs baseline: 1.3022x; 1.3022x over previous
#include <cuda_runtime.h>
#include <cuda_bf16.h>
#include <math.h>

// Shapes (fixed by the problem)
#define NQ   10
#define NL   4
#define NG   (NL * NQ)   // 40 single-qubit gates
#define NDIM 1024        // 2^NQ amplitudes
#define FFN  4096
#define EDIM 1024
#define NTOK 16384       // B*T

// Scratch (allocation-free rule: __device__ globals)
__device__ __align__(16) float g_h[FFN];
__device__ __align__(16) float g_y[EDIM];

__device__ __forceinline__ float2 cmul(float2 a, float2 b) {
    return make_float2(fmaf(a.x, b.x, -a.y * b.y), fmaf(a.x, b.y, a.y * b.x));
}
__device__ __forceinline__ float2 cfma2(float2 u, float2 a, float2 v, float2 b) {
    float re = fmaf(u.x, a.x, -u.y * a.y);
    re = fmaf(v.x, b.x, re);
    re = fmaf(-v.y, b.y, re);
    float im = fmaf(u.x, a.y, u.y * a.x);
    im = fmaf(v.x, b.y, im);
    im = fmaf(v.y, b.x, im);
    return make_float2(re, im);
}

// padded smem index for stride-16 gathers (<=2-way conflicts)
#define SIDX(i) ((i) + ((i) >> 4))
#define STSZ    (NDIM + NDIM / 16 + 8)

// ---------------------------------------------------------------------------
// Kernel A: 10-qubit statevector, 512 threads x 2 amplitudes (amp t, t+512).
// Bit 9 (= qubit 0) is the register bit -> qubit-0 gate is thread-local.
// Layout A: lane bits 4..0 = index bits 4..0  (qubits 5..9 via shfl)
// Layout B: lane bits 4..1 = index bits 8..5  (qubits 1..4 via shfl),
//           lane bit 0 = index bit 4, warp bits = index bits 3..0.
// Per layer: [q0 local + q5..9 shfl] -> transpose -> [q1..4 shfl]
//            -> CNOT-ring permutation fused with transpose-back.
// ---------------------------------------------------------------------------
__global__ void __launch_bounds__(512, 1)
circuit_h_kernel(const float* __restrict__ params,
                 const float* __restrict__ W1,
                 const float* __restrict__ b1) {
    __shared__ float2 U[NG][2];            // u00, u01 (u10/u11 by conjugation)
    __shared__ float2 st[2][STSZ];         // double-buffered, padded
    __shared__ float  wsum[16][NQ];
    __shared__ float  zsh[16];

    const int t    = threadIdx.x;          // 0..511 (9 bits)
    const int lane = t & 31;
    const int warp = t >> 5;               // 0..15

    // ---- build gate coefficients (threads 0..39) ------------------------
    if (t < NG) {
        const float t0 = params[t * 3 + 0];
        const float t1 = params[t * 3 + 1];
        const float t2 = params[t * 3 + 2];
        float cx, sx, cy, sy, cz, sz;
        sincosf(0.5f * t0, &sx, &cx);
        sincosf(0.5f * t1, &sy, &cy);
        sincosf(0.5f * t2, &sz, &cz);
        // M = Ry*Rx ; U = Rz*M ; u11 = conj(u00), u10 = -conj(u01)
        const float2 m00 = make_float2( cy * cx,  sy * sx);
        const float2 m01 = make_float2(-sy * cx, -cy * sx);
        const float2 ezm = make_float2(cz, -sz);
        U[t][0] = cmul(ezm, m00);
        U[t][1] = cmul(ezm, m01);
    }

    // ---- per-thread precompute ------------------------------------------
    // layout-B base index (r'=0): bits[8:5]=lane[4:1], bit4=lane[0], bits[3:0]=warp
    const int iB = ((lane >> 1) << 5) | ((lane & 1) << 4) | warp;

    // CNOT ring gather (composed): s_new[i] = s_old[C(i)], for both amps
    int Ct0 = t, Ct1 = t + 512;
    #pragma unroll
    for (int e = NQ - 1; e >= 0; e--) {
        const int c  = (e < NQ - 1) ? e : NQ - 1;
        const int tq = (e < NQ - 1) ? e + 1 : 0;
        const int cm = 1 << (NQ - 1 - c);
        const int tm = 1 << (NQ - 1 - tq);
        Ct0 ^= (Ct0 & cm) ? tm : 0;
        Ct1 ^= (Ct1 & cm) ? tm : 0;
    }

    // per-slot sign from lane bit (4-k); identical for layouts A and B
    float sgn[5];
    #pragma unroll
    for (int k = 0; k < 5; k++) sgn[k] = (lane & (16 >> k)) ? -1.0f : 1.0f;

    float2 a0 = make_float2(t == 0 ? 1.0f : 0.0f, 0.0f);
    float2 a1 = make_float2(0.0f, 0.0f);

    __syncthreads();   // U ready

    // ---- gate loop ------------------------------------------------------
    int cur = 0;
    #pragma unroll 1
    for (int l = 0; l < NL; l++) {
        // qubit 0: thread-local (register bit)
        {
            const int g = l * NQ;
            const float2 u00 = U[g][0], u01 = U[g][1];
            const float2 u10 = make_float2(-u01.x, u01.y);   // -conj(u01)
            const float2 u11 = make_float2( u00.x, -u00.y);  //  conj(u00)
            const float2 n0 = cfma2(u00, a0, u01, a1);
            const float2 n1 = cfma2(u10, a0, u11, a1);
            a0 = n0; a1 = n1;
        }
        // qubits 5..9 on lane bits (layout A)
        #pragma unroll
        for (int k = 0; k < 5; k++) {
            const int g = l * NQ + 5 + k;
            float2 u0 = U[g][0];
            float2 u1 = U[g][1];
            const float s = sgn[k];
            u0.y *= s; u1.x *= s;
            const int m = 16 >> k;
            float2 b0, b1v;
            b0.x  = __shfl_xor_sync(0xffffffffu, a0.x, m);
            b0.y  = __shfl_xor_sync(0xffffffffu, a0.y, m);
            b1v.x = __shfl_xor_sync(0xffffffffu, a1.x, m);
            b1v.y = __shfl_xor_sync(0xffffffffu, a1.y, m);
            a0 = cfma2(u0, a0, u1, b0);
            a1 = cfma2(u0, a1, u1, b1v);
        }
        // transpose A -> B
        st[cur][SIDX(t)]       = a0;
        st[cur][SIDX(t + 512)] = a1;
        __syncthreads();
        a0 = st[cur][SIDX(iB)];
        a1 = st[cur][SIDX(iB + 512)];
        cur ^= 1;
        // qubits 1..4 on lane bits 4..1 (layout B)
        #pragma unroll
        for (int k = 0; k < 4; k++) {
            const int g = l * NQ + 1 + k;
            float2 u0 = U[g][0];
            float2 u1 = U[g][1];
            const float s = sgn[k];
            u0.y *= s; u1.x *= s;
            const int m = 16 >> k;
            float2 b0, b1v;
            b0.x  = __shfl_xor_sync(0xffffffffu, a0.x, m);
            b0.y  = __shfl_xor_sync(0xffffffffu, a0.y, m);
            b1v.x = __shfl_xor_sync(0xffffffffu, a1.x, m);
            b1v.y = __shfl_xor_sync(0xffffffffu, a1.y, m);
            a0 = cfma2(u0, a0, u1, b0);
            a1 = cfma2(u0, a1, u1, b1v);
        }
        // CNOT ring + transpose back: write natural order, gather C(i)
        st[cur][SIDX(iB)]       = a0;
        st[cur][SIDX(iB + 512)] = a1;
        __syncthreads();
        a0 = st[cur][SIDX(Ct0)];
        a1 = st[cur][SIDX(Ct1)];
        cur ^= 1;
    }

    // ---- <Z_q> ----------------------------------------------------------
    const float p0 = fmaf(a0.x, a0.x, a0.y * a0.y);   // amp index t     (bit9=0)
    const float p1 = fmaf(a1.x, a1.x, a1.y * a1.y);   // amp index t+512 (bit9=1)
    #pragma unroll
    for (int q = 0; q < NQ; q++) {
        float v;
        if (q == 0) {
            v = p1;
        } else {
            const int mask = 1 << (NQ - 1 - q);
            v = (t & mask) ? (p0 + p1) : 0.0f;
        }
        #pragma unroll
        for (int o = 16; o > 0; o >>= 1) v += __shfl_xor_sync(0xffffffffu, v, o);
        if (lane == 0) wsum[warp][q] = v;
    }
    __syncthreads();
    if (t < NQ) {
        float s = 0.0f;
        #pragma unroll
        for (int w = 0; w < 16; w++) s += wsum[w][t];
        zsh[t] = 1.0f - 2.0f * s;
    }
    __syncthreads();

    float z[NQ];
    #pragma unroll
    for (int q = 0; q < NQ; q++) z[q] = zsh[q];

    // ---- h = relu(W1 @ z + b1); thread t -> rows 8t..8t+7 ---------------
    #pragma unroll
    for (int half = 0; half < 2; half++) {
        const float4* __restrict__ Wv = ((const float4*)W1) + (size_t)t * 20 + half * 10;
        float f[20];
        float acc[4];

        float4 v0 = Wv[0], v1 = Wv[1], v2 = Wv[2], v3 = Wv[3], v4 = Wv[4];
        f[0]=v0.x; f[1]=v0.y; f[2]=v0.z; f[3]=v0.w;
        f[4]=v1.x; f[5]=v1.y; f[6]=v1.z; f[7]=v1.w;
        f[8]=v2.x; f[9]=v2.y; f[10]=v2.z; f[11]=v2.w;
        f[12]=v3.x; f[13]=v3.y; f[14]=v3.z; f[15]=v3.w;
        f[16]=v4.x; f[17]=v4.y; f[18]=v4.z; f[19]=v4.w;
        acc[0] = 0.0f; acc[1] = 0.0f;
        #pragma unroll
        for (int q = 0; q < NQ; q++) acc[0] = fmaf(f[q],      z[q], acc[0]);
        #pragma unroll
        for (int q = 0; q < NQ; q++) acc[1] = fmaf(f[10 + q], z[q], acc[1]);

        v0 = Wv[5]; v1 = Wv[6]; v2 = Wv[7]; v3 = Wv[8]; v4 = Wv[9];
        f[0]=v0.x; f[1]=v0.y; f[2]=v0.z; f[3]=v0.w;
        f[4]=v1.x; f[5]=v1.y; f[6]=v1.z; f[7]=v1.w;
        f[8]=v2.x; f[9]=v2.y; f[10]=v2.z; f[11]=v2.w;
        f[12]=v3.x; f[13]=v3.y; f[14]=v3.z; f[15]=v3.w;
        f[16]=v4.x; f[17]=v4.y; f[18]=v4.z; f[19]=v4.w;
        acc[2] = 0.0f; acc[3] = 0.0f;
        #pragma unroll
        for (int q = 0; q < NQ; q++) acc[2] = fmaf(f[q],      z[q], acc[2]);
        #pragma unroll
        for (int q = 0; q < NQ; q++) acc[3] = fmaf(f[10 + q], z[q], acc[3]);

        const float4 bb = ((const float4*)b1)[2 * t + half];
        float4 hv;
        hv.x = fmaxf(acc[0] + bb.x, 0.0f);
        hv.y = fmaxf(acc[1] + bb.y, 0.0f);
        hv.z = fmaxf(acc[2] + bb.z, 0.0f);
        hv.w = fmaxf(acc[3] + bb.w, 0.0f);
        ((float4*)g_h)[2 * t + half] = hv;
    }
}

// ---------------------------------------------------------------------------
// Kernel B: y = W2 @ h + b2.  One block per output element (1024 blocks).
// ---------------------------------------------------------------------------
__global__ void __launch_bounds__(256)
matvec_kernel(const float* __restrict__ W2, const float* __restrict__ b2) {
    const int e = blockIdx.x;
    const int t = threadIdx.x;
    const float4* __restrict__ w4 = (const float4*)(W2 + (size_t)e * FFN);
    const float4* __restrict__ h4 = (const float4*)g_h;

    float acc = 0.0f;
    #pragma unroll
    for (int j = 0; j < 4; j++) {
        const float4 w = w4[t + 256 * j];
        const float4 h = h4[t + 256 * j];
        acc += w.x * h.x + w.y * h.y + w.z * h.z + w.w * h.w;
    }
    #pragma unroll
    for (int o = 16; o > 0; o >>= 1) acc += __shfl_down_sync(0xffffffffu, acc, o);

    __shared__ float ws[8];
    if ((t & 31) == 0) ws[t >> 5] = acc;
    __syncthreads();
    if (t < 8) {
        float v = ws[t];
        #pragma unroll
        for (int o = 4; o > 0; o >>= 1) v += __shfl_down_sync(0xffu, v, o);
        if (t == 0) g_y[e] = v + b2[e];
    }
}

// ---------------------------------------------------------------------------
// Kernel C: broadcast fill — 64MB of float4 stores (the HBM floor).
// ---------------------------------------------------------------------------
__global__ void __launch_bounds__(256)
fill_kernel(float4* __restrict__ out) {
    const int col = threadIdx.x;                 // float4 within row
    const float4 v = ((const float4*)g_y)[col];
    const size_t base = (size_t)blockIdx.x * 4;  // 4 rows per block
    #pragma unroll
    for (int r = 0; r < 4; r++) {
        out[(base + r) * (EDIM / 4) + col] = v;
    }
}

// ---------------------------------------------------------------------------
// inputs: 0=x, 1=W_in, 2=b_in, 3=params, 4=W1, 5=b1, 6=W2, 7=b2
// x / W_in / b_in are dead in the reference.
// ---------------------------------------------------------------------------
extern "C" void kernel_launch(void* const* d_in, const int* in_sizes, int n_in,
                              void* d_out, int out_size) {
    const float* params = (const float*)d_in[3];
    const float* W1     = (const float*)d_in[4];
    const float* b1     = (const float*)d_in[5];
    const float* W2     = (const float*)d_in[6];
    const float* b2     = (const float*)d_in[7];
    float* out = (float*)d_out;

    circuit_h_kernel<<<1, 512>>>(params, W1, b1);
    matvec_kernel<<<EDIM, 256>>>(W2, b2);
    fill_kernel<<<NTOK / 4, 256>>>((float4*)out);
}

// round 7
// speedup vs baseline: 1.3944x; 1.0708x over previous
#include <cuda_runtime.h>
#include <cuda_bf16.h>
#include <math.h>

// Shapes (fixed by the problem)
#define NQ   10
#define NL   4
#define NG   (NL * NQ)   // 40 single-qubit gates
#define NDIM 1024        // 2^NQ amplitudes
#define FFN  4096
#define EDIM 1024
#define NTOK 16384       // B*T
#define GRID_A 33        // 0..7 h-rows, 8..31 W2 prefetch, 32 circuit

// Persistent scratch / flags (monotonic across graph replays: no reset needed)
__device__ int g_entry = 0;
__device__ int g_zflag = 0;
__device__ float g_z[16];
__device__ __align__(16) float g_h[FFN];
__device__ __align__(16) float g_y[EDIM];

__device__ __forceinline__ float2 cmul(float2 a, float2 b) {
    return make_float2(fmaf(a.x, b.x, -a.y * b.y), fmaf(a.x, b.y, a.y * b.x));
}
__device__ __forceinline__ float2 cfma2(float2 u, float2 a, float2 v, float2 b) {
    float re = fmaf(u.x, a.x, -u.y * a.y);
    re = fmaf(v.x, b.x, re);
    re = fmaf(-v.y, b.y, re);
    float im = fmaf(u.x, a.y, u.y * a.x);
    im = fmaf(v.x, b.y, im);
    im = fmaf(v.y, b.x, im);
    return make_float2(re, im);
}
__device__ __forceinline__ void l2_prefetch(const void* p) {
    asm volatile("prefetch.global.L2 [%0];" :: "l"(p));
}

// padded smem index for stride-16 gathers
#define SIDX(i) ((i) + ((i) >> 4))
#define STSZ    (NDIM + NDIM / 16 + 8)

// ---------------------------------------------------------------------------
// Kernel A: block 32 = circuit -> g_z (+flag). blocks 0..7 = h rows (W1 read
// hidden behind the circuit). blocks 8..31 = W2 L2-prefetch (no wait).
// ---------------------------------------------------------------------------
__global__ void __launch_bounds__(512, 1)
circuit_h_kernel(const float* __restrict__ params,
                 const float* __restrict__ W1,
                 const float* __restrict__ b1,
                 const float* __restrict__ W2) {
    __shared__ float2 U[NG][2];
    __shared__ float2 st[2][STSZ];
    __shared__ float  wsum[16][NQ];
    __shared__ int    s_epoch;

    const int t    = threadIdx.x;          // 0..511
    const int b    = blockIdx.x;
    const int lane = t & 31;
    const int warp = t >> 5;

    if (t == 0) s_epoch = atomicAdd(&g_entry, 1) / GRID_A;
    __syncthreads();
    const int target = s_epoch + 1;

    if (b < 8) {
        // ============ h rows: load W1 row while circuit runs ============
        const int j = b * 512 + t;               // row 0..4095
        const float* __restrict__ w = W1 + (size_t)j * NQ;
        float f[NQ];
        #pragma unroll
        for (int q = 0; q < NQ; q++) f[q] = w[q];
        const float bias = b1[j];

        if (t == 0) {
            while (((volatile int*)&g_zflag)[0] < target) __nanosleep(32);
        }
        __syncthreads();
        __threadfence();

        float acc = bias;
        #pragma unroll
        for (int q = 0; q < NQ; q++) acc = fmaf(f[q], g_z[q], acc);
        g_h[j] = fmaxf(acc, 0.0f);
        return;
    }

    if (b < 32) {
        // ============ W2 prefetch into L2 (16MB / 24 blocks) ============
        const int pb = b - 8;                     // 0..23
        const char* base = (const char*)W2;
        const size_t lines = (size_t)EDIM * FFN * 4 / 128;   // 131072
        // each block: lines [pb*5462, ...) strided by 512 threads
        #pragma unroll
        for (int i = 0; i < 11; i++) {
            const size_t ln = (size_t)pb * 5462 + (size_t)i * 512 + t;
            if (ln < lines) l2_prefetch(base + ln * 128);
        }
        return;
    }

    // ===================== circuit (block 32) =====================
    if (t < NG) {
        const float t0 = params[t * 3 + 0];
        const float t1 = params[t * 3 + 1];
        const float t2 = params[t * 3 + 2];
        float cx, sx, cy, sy, cz, sz;
        sincosf(0.5f * t0, &sx, &cx);
        sincosf(0.5f * t1, &sy, &cy);
        sincosf(0.5f * t2, &sz, &cz);
        const float2 m00 = make_float2( cy * cx,  sy * sx);
        const float2 m01 = make_float2(-sy * cx, -cy * sx);
        const float2 ezm = make_float2(cz, -sz);
        U[t][0] = cmul(ezm, m00);
        U[t][1] = cmul(ezm, m01);
    }

    // layout-B base index: bits[8:5]=lane[4:1], bit4=lane[0], bits[3:0]=warp
    const int iB = ((lane >> 1) << 5) | ((lane & 1) << 4) | warp;

    int Ct0 = t, Ct1 = t + 512;
    #pragma unroll
    for (int e = NQ - 1; e >= 0; e--) {
        const int c  = (e < NQ - 1) ? e : NQ - 1;
        const int tq = (e < NQ - 1) ? e + 1 : 0;
        const int cm = 1 << (NQ - 1 - c);
        const int tm = 1 << (NQ - 1 - tq);
        Ct0 ^= (Ct0 & cm) ? tm : 0;
        Ct1 ^= (Ct1 & cm) ? tm : 0;
    }
    float sgn[5];
    #pragma unroll
    for (int k = 0; k < 5; k++) sgn[k] = (lane & (16 >> k)) ? -1.0f : 1.0f;

    float2 a0 = make_float2(t == 0 ? 1.0f : 0.0f, 0.0f);
    float2 a1 = make_float2(0.0f, 0.0f);

    __syncthreads();

    int cur = 0;
    #pragma unroll 1
    for (int l = 0; l < NL; l++) {
        // qubit 0: register bit (thread-local)
        {
            const int g = l * NQ;
            const float2 u00 = U[g][0], u01 = U[g][1];
            const float2 u10 = make_float2(-u01.x, u01.y);
            const float2 u11 = make_float2( u00.x, -u00.y);
            const float2 n0 = cfma2(u00, a0, u01, a1);
            const float2 n1 = cfma2(u10, a0, u11, a1);
            a0 = n0; a1 = n1;
        }
        // qubits 5..9 on lane bits (layout A)
        #pragma unroll
        for (int k = 0; k < 5; k++) {
            const int g = l * NQ + 5 + k;
            float2 u0 = U[g][0];
            float2 u1 = U[g][1];
            const float s = sgn[k];
            u0.y *= s; u1.x *= s;
            const int m = 16 >> k;
            float2 b0v, b1v;
            b0v.x = __shfl_xor_sync(0xffffffffu, a0.x, m);
            b0v.y = __shfl_xor_sync(0xffffffffu, a0.y, m);
            b1v.x = __shfl_xor_sync(0xffffffffu, a1.x, m);
            b1v.y = __shfl_xor_sync(0xffffffffu, a1.y, m);
            a0 = cfma2(u0, a0, u1, b0v);
            a1 = cfma2(u0, a1, u1, b1v);
        }
        // transpose A -> B
        st[cur][SIDX(t)]       = a0;
        st[cur][SIDX(t + 512)] = a1;
        __syncthreads();
        a0 = st[cur][SIDX(iB)];
        a1 = st[cur][SIDX(iB + 512)];
        cur ^= 1;
        // qubits 1..4 on lane bits 4..1 (layout B)
        #pragma unroll
        for (int k = 0; k < 4; k++) {
            const int g = l * NQ + 1 + k;
            float2 u0 = U[g][0];
            float2 u1 = U[g][1];
            const float s = sgn[k];
            u0.y *= s; u1.x *= s;
            const int m = 16 >> k;
            float2 b0v, b1v;
            b0v.x = __shfl_xor_sync(0xffffffffu, a0.x, m);
            b0v.y = __shfl_xor_sync(0xffffffffu, a0.y, m);
            b1v.x = __shfl_xor_sync(0xffffffffu, a1.x, m);
            b1v.y = __shfl_xor_sync(0xffffffffu, a1.y, m);
            a0 = cfma2(u0, a0, u1, b0v);
            a1 = cfma2(u0, a1, u1, b1v);
        }
        // CNOT ring + transpose back
        st[cur][SIDX(iB)]       = a0;
        st[cur][SIDX(iB + 512)] = a1;
        __syncthreads();
        a0 = st[cur][SIDX(Ct0)];
        a1 = st[cur][SIDX(Ct1)];
        cur ^= 1;
    }

    // <Z_q>
    const float p0 = fmaf(a0.x, a0.x, a0.y * a0.y);
    const float p1 = fmaf(a1.x, a1.x, a1.y * a1.y);
    #pragma unroll
    for (int q = 0; q < NQ; q++) {
        float v;
        if (q == 0) {
            v = p1;
        } else {
            const int mask = 1 << (NQ - 1 - q);
            v = (t & mask) ? (p0 + p1) : 0.0f;
        }
        #pragma unroll
        for (int o = 16; o > 0; o >>= 1) v += __shfl_xor_sync(0xffffffffu, v, o);
        if (lane == 0) wsum[warp][q] = v;
    }
    __syncthreads();
    if (t < NQ) {
        float s = 0.0f;
        #pragma unroll
        for (int w = 0; w < 16; w++) s += wsum[w][t];
        g_z[t] = 1.0f - 2.0f * s;
    }
    __syncthreads();
    if (t == 0) {
        __threadfence();
        atomicMax(&g_zflag, target);   // release; monotonic
    }
}

// ---------------------------------------------------------------------------
// Kernel B: y = W2 @ h + b2.  One block per output element (1024 blocks).
// W2 is L2-warm from the prefetch blocks.
// ---------------------------------------------------------------------------
__global__ void __launch_bounds__(256)
matvec_kernel(const float* __restrict__ W2, const float* __restrict__ b2) {
    const int e = blockIdx.x;
    const int t = threadIdx.x;
    const float4* __restrict__ w4 = (const float4*)(W2 + (size_t)e * FFN);
    const float4* __restrict__ h4 = (const float4*)g_h;

    float acc = 0.0f;
    #pragma unroll
    for (int j = 0; j < 4; j++) {
        const float4 w = w4[t + 256 * j];
        const float4 h = h4[t + 256 * j];
        acc += w.x * h.x + w.y * h.y + w.z * h.z + w.w * h.w;
    }
    #pragma unroll
    for (int o = 16; o > 0; o >>= 1) acc += __shfl_down_sync(0xffffffffu, acc, o);

    __shared__ float ws[8];
    if ((t & 31) == 0) ws[t >> 5] = acc;
    __syncthreads();
    if (t < 8) {
        float v = ws[t];
        #pragma unroll
        for (int o = 4; o > 0; o >>= 1) v += __shfl_down_sync(0xffu, v, o);
        if (t == 0) g_y[e] = v + b2[e];
    }
}

// ---------------------------------------------------------------------------
// Kernel C: broadcast fill — 64MB of float4 stores (the HBM floor).
// ---------------------------------------------------------------------------
__global__ void __launch_bounds__(256)
fill_kernel(float4* __restrict__ out) {
    const int col = threadIdx.x;
    const float4 v = ((const float4*)g_y)[col];
    const size_t base = (size_t)blockIdx.x * 4;
    #pragma unroll
    for (int r = 0; r < 4; r++) {
        out[(base + r) * (EDIM / 4) + col] = v;
    }
}

// ---------------------------------------------------------------------------
// inputs: 0=x, 1=W_in, 2=b_in, 3=params, 4=W1, 5=b1, 6=W2, 7=b2
// x / W_in / b_in are dead in the reference.
// ---------------------------------------------------------------------------
extern "C" void kernel_launch(void* const* d_in, const int* in_sizes, int n_in,
                              void* d_out, int out_size) {
    const float* params = (const float*)d_in[3];
    const float* W1     = (const float*)d_in[4];
    const float* b1     = (const float*)d_in[5];
    const float* W2     = (const float*)d_in[6];
    const float* b2     = (const float*)d_in[7];
    float* out = (float*)d_out;

    circuit_h_kernel<<<GRID_A, 512>>>(params, W1, b1, W2);
    matvec_kernel<<<EDIM, 256>>>(W2, b2);
    fill_kernel<<<NTOK / 4, 256>>>((float4*)out);
}

// round 8
// speedup vs baseline: 1.4087x; 1.0102x over previous
#include <cuda_runtime.h>
#include <cuda_bf16.h>
#include <math.h>

// Shapes (fixed by the problem)
#define NQ   10
#define NL   4
#define NG   (NL * NQ)   // 40 single-qubit gates
#define NDIM 1024        // 2^NQ amplitudes
#define FFN  4096
#define EDIM 1024
#define NTOK 16384       // B*T
#define GRID_A 148       // 0..7 h-rows, 8..146 W2 prefetch (139), 147 circuit

// Persistent scratch / flags (monotonic across graph replays: no reset needed)
__device__ int g_entry = 0;
__device__ int g_zflag = 0;
__device__ float g_z[16];
__device__ __align__(16) float g_h[FFN];
__device__ __align__(16) float g_y[EDIM];

__device__ __forceinline__ float2 cmul(float2 a, float2 b) {
    return make_float2(fmaf(a.x, b.x, -a.y * b.y), fmaf(a.x, b.y, a.y * b.x));
}
__device__ __forceinline__ float2 cfma2(float2 u, float2 a, float2 v, float2 b) {
    float re = fmaf(u.x, a.x, -u.y * a.y);
    re = fmaf(v.x, b.x, re);
    re = fmaf(-v.y, b.y, re);
    float im = fmaf(u.x, a.y, u.y * a.x);
    im = fmaf(v.x, b.y, im);
    im = fmaf(v.y, b.x, im);
    return make_float2(re, im);
}
__device__ __forceinline__ void l2_prefetch(const void* p) {
    asm volatile("prefetch.global.L2 [%0];" :: "l"(p));
}

// padded smem index for stride-16 gathers
#define SIDX(i) ((i) + ((i) >> 4))
#define STSZ    (NDIM + NDIM / 16 + 8)

// ---------------------------------------------------------------------------
// Kernel A: block 147 = circuit -> g_z (+flag). blocks 0..7 = h rows (W1 read
// hidden behind the circuit). blocks 8..146 = W2 L2-prefetch at full-chip MLP.
// ---------------------------------------------------------------------------
__global__ void __launch_bounds__(512, 1)
circuit_h_kernel(const float* __restrict__ params,
                 const float* __restrict__ W1,
                 const float* __restrict__ b1,
                 const float* __restrict__ W2) {
    __shared__ float2 U[NG][2];
    __shared__ float2 st[2][STSZ];
    __shared__ float  wsum[16][NQ];
    __shared__ int    s_epoch;

    const int t    = threadIdx.x;          // 0..511
    const int b    = blockIdx.x;
    const int lane = t & 31;
    const int warp = t >> 5;

    if (b < 8 || b == GRID_A - 1) {
        if (t == 0) s_epoch = atomicAdd(&g_entry, 1) / 9;   // 9 sync participants
        __syncthreads();
    }
    const int target = (b < 8 || b == GRID_A - 1) ? (s_epoch + 1) : 0;

    if (b < 8) {
        // ============ h rows: load W1 row while circuit runs ============
        const int j = b * 512 + t;               // row 0..4095
        const float* __restrict__ w = W1 + (size_t)j * NQ;
        float f[NQ];
        #pragma unroll
        for (int q = 0; q < NQ; q++) f[q] = w[q];
        const float bias = b1[j];

        if (t == 0) {
            while (((volatile int*)&g_zflag)[0] < target) __nanosleep(32);
        }
        __syncthreads();
        __threadfence();

        float acc = bias;
        #pragma unroll
        for (int q = 0; q < NQ; q++) acc = fmaf(f[q], g_z[q], acc);
        g_h[j] = fmaxf(acc, 0.0f);
        return;
    }

    if (b < GRID_A - 1) {
        // ===== W2 prefetch into L2: 139 blocks, full-chip bandwidth =====
        const int pb = b - 8;                                // 0..138
        const size_t gid = (size_t)pb * 512 + t;             // 0..71167
        const char* base = (const char*)W2;
        const size_t lines = (size_t)EDIM * FFN * 4 / 128;   // 131072
        l2_prefetch(base + gid * 128);
        const size_t ln2 = gid + (size_t)139 * 512;
        if (ln2 < lines) l2_prefetch(base + ln2 * 128);
        return;
    }

    // ===================== circuit (block 147) =====================
    if (t < NG) {
        const float t0 = params[t * 3 + 0];
        const float t1 = params[t * 3 + 1];
        const float t2 = params[t * 3 + 2];
        float cx, sx, cy, sy, cz, sz;
        sincosf(0.5f * t0, &sx, &cx);
        sincosf(0.5f * t1, &sy, &cy);
        sincosf(0.5f * t2, &sz, &cz);
        const float2 m00 = make_float2( cy * cx,  sy * sx);
        const float2 m01 = make_float2(-sy * cx, -cy * sx);
        const float2 ezm = make_float2(cz, -sz);
        U[t][0] = cmul(ezm, m00);
        U[t][1] = cmul(ezm, m01);
    }

    // layout-B base index: bits[8:5]=lane[4:1], bit4=lane[0], bits[3:0]=warp
    const int iB = ((lane >> 1) << 5) | ((lane & 1) << 4) | warp;

    int Ct0 = t, Ct1 = t + 512;
    #pragma unroll
    for (int e = NQ - 1; e >= 0; e--) {
        const int c  = (e < NQ - 1) ? e : NQ - 1;
        const int tq = (e < NQ - 1) ? e + 1 : 0;
        const int cm = 1 << (NQ - 1 - c);
        const int tm = 1 << (NQ - 1 - tq);
        Ct0 ^= (Ct0 & cm) ? tm : 0;
        Ct1 ^= (Ct1 & cm) ? tm : 0;
    }
    float sgn[5];
    #pragma unroll
    for (int k = 0; k < 5; k++) sgn[k] = (lane & (16 >> k)) ? -1.0f : 1.0f;

    float2 a0 = make_float2(t == 0 ? 1.0f : 0.0f, 0.0f);
    float2 a1 = make_float2(0.0f, 0.0f);

    __syncthreads();

    int cur = 0;
    #pragma unroll 1
    for (int l = 0; l < NL; l++) {
        // qubit 0: register bit (thread-local)
        {
            const int g = l * NQ;
            const float2 u00 = U[g][0], u01 = U[g][1];
            const float2 u10 = make_float2(-u01.x, u01.y);
            const float2 u11 = make_float2( u00.x, -u00.y);
            const float2 n0 = cfma2(u00, a0, u01, a1);
            const float2 n1 = cfma2(u10, a0, u11, a1);
            a0 = n0; a1 = n1;
        }
        // qubits 5..9 on lane bits (layout A)
        #pragma unroll
        for (int k = 0; k < 5; k++) {
            const int g = l * NQ + 5 + k;
            float2 u0 = U[g][0];
            float2 u1 = U[g][1];
            const float s = sgn[k];
            u0.y *= s; u1.x *= s;
            const int m = 16 >> k;
            float2 b0v, b1v;
            b0v.x = __shfl_xor_sync(0xffffffffu, a0.x, m);
            b0v.y = __shfl_xor_sync(0xffffffffu, a0.y, m);
            b1v.x = __shfl_xor_sync(0xffffffffu, a1.x, m);
            b1v.y = __shfl_xor_sync(0xffffffffu, a1.y, m);
            a0 = cfma2(u0, a0, u1, b0v);
            a1 = cfma2(u0, a1, u1, b1v);
        }
        // transpose A -> B
        st[cur][SIDX(t)]       = a0;
        st[cur][SIDX(t + 512)] = a1;
        __syncthreads();
        a0 = st[cur][SIDX(iB)];
        a1 = st[cur][SIDX(iB + 512)];
        cur ^= 1;
        // qubits 1..4 on lane bits 4..1 (layout B)
        #pragma unroll
        for (int k = 0; k < 4; k++) {
            const int g = l * NQ + 1 + k;
            float2 u0 = U[g][0];
            float2 u1 = U[g][1];
            const float s = sgn[k];
            u0.y *= s; u1.x *= s;
            const int m = 16 >> k;
            float2 b0v, b1v;
            b0v.x = __shfl_xor_sync(0xffffffffu, a0.x, m);
            b0v.y = __shfl_xor_sync(0xffffffffu, a0.y, m);
            b1v.x = __shfl_xor_sync(0xffffffffu, a1.x, m);
            b1v.y = __shfl_xor_sync(0xffffffffu, a1.y, m);
            a0 = cfma2(u0, a0, u1, b0v);
            a1 = cfma2(u0, a1, u1, b1v);
        }
        // CNOT ring + transpose back
        st[cur][SIDX(iB)]       = a0;
        st[cur][SIDX(iB + 512)] = a1;
        __syncthreads();
        a0 = st[cur][SIDX(Ct0)];
        a1 = st[cur][SIDX(Ct1)];
        cur ^= 1;
    }

    // <Z_q>
    const float p0 = fmaf(a0.x, a0.x, a0.y * a0.y);
    const float p1 = fmaf(a1.x, a1.x, a1.y * a1.y);
    #pragma unroll
    for (int q = 0; q < NQ; q++) {
        float v;
        if (q == 0) {
            v = p1;
        } else {
            const int mask = 1 << (NQ - 1 - q);
            v = (t & mask) ? (p0 + p1) : 0.0f;
        }
        #pragma unroll
        for (int o = 16; o > 0; o >>= 1) v += __shfl_xor_sync(0xffffffffu, v, o);
        if (lane == 0) wsum[warp][q] = v;
    }
    __syncthreads();
    if (t < NQ) {
        float s = 0.0f;
        #pragma unroll
        for (int w = 0; w < 16; w++) s += wsum[w][t];
        g_z[t] = 1.0f - 2.0f * s;
    }
    __syncthreads();
    if (t == 0) {
        __threadfence();
        atomicMax(&g_zflag, target);   // release; monotonic
    }
}

// ---------------------------------------------------------------------------
// Kernel B: y = W2 @ h + b2.  One block per output element (1024 blocks).
// W2 is L2-warm from the prefetch blocks.
// ---------------------------------------------------------------------------
__global__ void __launch_bounds__(256)
matvec_kernel(const float* __restrict__ W2, const float* __restrict__ b2) {
    const int e = blockIdx.x;
    const int t = threadIdx.x;
    const float4* __restrict__ w4 = (const float4*)(W2 + (size_t)e * FFN);
    const float4* __restrict__ h4 = (const float4*)g_h;

    float acc = 0.0f;
    #pragma unroll
    for (int j = 0; j < 4; j++) {
        const float4 w = w4[t + 256 * j];
        const float4 h = h4[t + 256 * j];
        acc += w.x * h.x + w.y * h.y + w.z * h.z + w.w * h.w;
    }
    #pragma unroll
    for (int o = 16; o > 0; o >>= 1) acc += __shfl_down_sync(0xffffffffu, acc, o);

    __shared__ float ws[8];
    if ((t & 31) == 0) ws[t >> 5] = acc;
    __syncthreads();
    if (t < 8) {
        float v = ws[t];
        #pragma unroll
        for (int o = 4; o > 0; o >>= 1) v += __shfl_down_sync(0xffu, v, o);
        if (t == 0) g_y[e] = v + b2[e];
    }
}

// ---------------------------------------------------------------------------
// Kernel C: broadcast fill — 64MB of float4 stores (the HBM floor).
// ---------------------------------------------------------------------------
__global__ void __launch_bounds__(256)
fill_kernel(float4* __restrict__ out) {
    const int col = threadIdx.x;
    const float4 v = ((const float4*)g_y)[col];
    const size_t base = (size_t)blockIdx.x * 4;
    #pragma unroll
    for (int r = 0; r < 4; r++) {
        out[(base + r) * (EDIM / 4) + col] = v;
    }
}

// ---------------------------------------------------------------------------
// inputs: 0=x, 1=W_in, 2=b_in, 3=params, 4=W1, 5=b1, 6=W2, 7=b2
// x / W_in / b_in are dead in the reference.
// ---------------------------------------------------------------------------
extern "C" void kernel_launch(void* const* d_in, const int* in_sizes, int n_in,
                              void* d_out, int out_size) {
    const float* params = (const float*)d_in[3];
    const float* W1     = (const float*)d_in[4];
    const float* b1     = (const float*)d_in[5];
    const float* W2     = (const float*)d_in[6];
    const float* b2     = (const float*)d_in[7];
    float* out = (float*)d_out;

    circuit_h_kernel<<<GRID_A, 512>>>(params, W1, b1, W2);
    matvec_kernel<<<EDIM, 256>>>(W2, b2);
    fill_kernel<<<NTOK / 4, 256>>>((float4*)out);
}

// round 9
// speedup vs baseline: 1.5319x; 1.0875x over previous
#include <cuda_runtime.h>
#include <cuda_bf16.h>
#include <math.h>

// Shapes (fixed by the problem)
#define NQ   10
#define NL   4
#define NG   (NL * NQ)   // 40 single-qubit gates
#define NDIM 1024        // 2^NQ amplitudes
#define FFN  4096
#define EDIM 1024
#define NTOK 16384       // B*T
#define GRID_A 137       // 0..7 h-rows, 8..135 matvec (128), 136 circuit

// Persistent scratch / flags (monotonic across graph replays: no reset needed)
__device__ int g_entry = 0;
__device__ int g_zflag = 0;
__device__ int g_hcnt  = 0;
__device__ float g_z[16];
__device__ __align__(16) float g_h[FFN];
__device__ __align__(16) float g_y[EDIM];

__device__ __forceinline__ float2 cmul(float2 a, float2 b) {
    return make_float2(fmaf(a.x, b.x, -a.y * b.y), fmaf(a.x, b.y, a.y * b.x));
}
__device__ __forceinline__ float2 cfma2(float2 u, float2 a, float2 v, float2 b) {
    float re = fmaf(u.x, a.x, -u.y * a.y);
    re = fmaf(v.x, b.x, re);
    re = fmaf(-v.y, b.y, re);
    float im = fmaf(u.x, a.y, u.y * a.x);
    im = fmaf(v.x, b.y, im);
    im = fmaf(v.y, b.x, im);
    return make_float2(re, im);
}
__device__ __forceinline__ void l2_prefetch(const void* p) {
    asm volatile("prefetch.global.L2 [%0];" :: "l"(p));
}

// padded smem index for stride-16 gathers
#define SIDX(i) ((i) + ((i) >> 4))
#define STSZ    (NDIM + NDIM / 16 + 8)

// ---------------------------------------------------------------------------
// Kernel A (everything except the fill):
//   block 136 : 10-qubit circuit -> g_z, release z-flag
//   blocks 0..7: W1 rows in regs during circuit -> h = relu(W1 z + b1) -> g_h,
//                bump h-counter
//   blocks 8..135: own 8 W2 rows -> L2 prefetch + register load during circuit,
//                spin h-counter -> y slice -> g_y
// ---------------------------------------------------------------------------
__global__ void __launch_bounds__(512, 1)
circuit_h_y_kernel(const float* __restrict__ params,
                   const float* __restrict__ W1,
                   const float* __restrict__ b1,
                   const float* __restrict__ W2,
                   const float* __restrict__ b2) {
    __shared__ float2 U[NG][2];
    __shared__ float2 st[2][STSZ];
    __shared__ float  wsum[16][NQ];
    __shared__ float  red[16];
    __shared__ int    s_epoch;

    const int t    = threadIdx.x;          // 0..511
    const int b    = blockIdx.x;
    const int lane = t & 31;
    const int warp = t >> 5;

    if (t == 0) s_epoch = atomicAdd(&g_entry, 1) / GRID_A;
    __syncthreads();
    const int target = s_epoch + 1;

    if (b < 8) {
        // ============ h rows: W1 row in regs while circuit runs ============
        const int j = b * 512 + t;               // row 0..4095
        const float* __restrict__ w = W1 + (size_t)j * NQ;
        float f[NQ];
        #pragma unroll
        for (int q = 0; q < NQ; q++) f[q] = w[q];
        const float bias = b1[j];

        if (t == 0) {
            while (((volatile int*)&g_zflag)[0] < target) __nanosleep(32);
        }
        __syncthreads();
        __threadfence();

        float acc = bias;
        #pragma unroll
        for (int q = 0; q < NQ; q++) acc = fmaf(f[q], g_z[q], acc);
        g_h[j] = fmaxf(acc, 0.0f);
        __threadfence();
        __syncthreads();
        if (t == 0) atomicAdd(&g_hcnt, 1);
        return;
    }

    if (b < 136) {
        // ========= matvec blocks: y[8pb .. 8pb+8), W2 rows preloaded =========
        const int pb = b - 8;                     // 0..127
        const int g  = t >> 6;                    // 0..7 output within block
        const int j  = t & 63;
        const int e  = pb * 8 + g;
        const float4* __restrict__ w4 = (const float4*)(W2 + (size_t)e * FFN);

        // prefetch (robust if the reg loads get sunk) + register load
        #pragma unroll
        for (int k = 0; k < 16; k++) l2_prefetch(&w4[j + 64 * k]);
        if (t == 0) l2_prefetch(b2 + pb * 8);
        float4 w[16];
        #pragma unroll
        for (int k = 0; k < 16; k++) w[k] = w4[j + 64 * k];

        // wait for all 8 h blocks
        if (t == 0) {
            const int ht = 8 * target;
            while (((volatile int*)&g_hcnt)[0] < ht) __nanosleep(32);
        }
        __syncthreads();
        __threadfence();

        const float4* __restrict__ h4 = (const float4*)g_h;
        float acc = 0.0f;
        #pragma unroll
        for (int k = 0; k < 16; k++) {
            const float4 h = h4[j + 64 * k];
            acc += w[k].x * h.x + w[k].y * h.y + w[k].z * h.z + w[k].w * h.w;
        }
        #pragma unroll
        for (int o = 16; o > 0; o >>= 1) acc += __shfl_down_sync(0xffffffffu, acc, o);
        if (lane == 0) red[warp] = acc;
        __syncthreads();
        if (t < 8) g_y[pb * 8 + t] = red[2 * t] + red[2 * t + 1] + b2[pb * 8 + t];
        return;
    }

    // ===================== circuit (block 136) =====================
    if (t < NG) {
        const float t0 = params[t * 3 + 0];
        const float t1 = params[t * 3 + 1];
        const float t2 = params[t * 3 + 2];
        float cx, sx, cy, sy, cz, sz;
        __sincosf(0.5f * t0, &sx, &cx);
        __sincosf(0.5f * t1, &sy, &cy);
        __sincosf(0.5f * t2, &sz, &cz);
        const float2 m00 = make_float2( cy * cx,  sy * sx);
        const float2 m01 = make_float2(-sy * cx, -cy * sx);
        const float2 ezm = make_float2(cz, -sz);
        U[t][0] = cmul(ezm, m00);
        U[t][1] = cmul(ezm, m01);
    }

    // layout-B base index: bits[8:5]=lane[4:1], bit4=lane[0], bits[3:0]=warp
    const int iB = ((lane >> 1) << 5) | ((lane & 1) << 4) | warp;

    int Ct0 = t, Ct1 = t + 512;
    #pragma unroll
    for (int e = NQ - 1; e >= 0; e--) {
        const int c  = (e < NQ - 1) ? e : NQ - 1;
        const int tq = (e < NQ - 1) ? e + 1 : 0;
        const int cm = 1 << (NQ - 1 - c);
        const int tm = 1 << (NQ - 1 - tq);
        Ct0 ^= (Ct0 & cm) ? tm : 0;
        Ct1 ^= (Ct1 & cm) ? tm : 0;
    }
    float sgn[5];
    #pragma unroll
    for (int k = 0; k < 5; k++) sgn[k] = (lane & (16 >> k)) ? -1.0f : 1.0f;

    float2 a0 = make_float2(t == 0 ? 1.0f : 0.0f, 0.0f);
    float2 a1 = make_float2(0.0f, 0.0f);

    __syncthreads();

    int cur = 0;
    #pragma unroll 1
    for (int l = 0; l < NL; l++) {
        // qubit 0: register bit (thread-local)
        {
            const int g = l * NQ;
            const float2 u00 = U[g][0], u01 = U[g][1];
            const float2 u10 = make_float2(-u01.x, u01.y);
            const float2 u11 = make_float2( u00.x, -u00.y);
            const float2 n0 = cfma2(u00, a0, u01, a1);
            const float2 n1 = cfma2(u10, a0, u11, a1);
            a0 = n0; a1 = n1;
        }
        // qubits 5..9 on lane bits (layout A)
        #pragma unroll
        for (int k = 0; k < 5; k++) {
            const int g = l * NQ + 5 + k;
            float2 u0 = U[g][0];
            float2 u1 = U[g][1];
            const float s = sgn[k];
            u0.y *= s; u1.x *= s;
            const int m = 16 >> k;
            float2 b0v, b1v;
            b0v.x = __shfl_xor_sync(0xffffffffu, a0.x, m);
            b0v.y = __shfl_xor_sync(0xffffffffu, a0.y, m);
            b1v.x = __shfl_xor_sync(0xffffffffu, a1.x, m);
            b1v.y = __shfl_xor_sync(0xffffffffu, a1.y, m);
            a0 = cfma2(u0, a0, u1, b0v);
            a1 = cfma2(u0, a1, u1, b1v);
        }
        // transpose A -> B
        st[cur][SIDX(t)]       = a0;
        st[cur][SIDX(t + 512)] = a1;
        __syncthreads();
        a0 = st[cur][SIDX(iB)];
        a1 = st[cur][SIDX(iB + 512)];
        cur ^= 1;
        // qubits 1..4 on lane bits 4..1 (layout B)
        #pragma unroll
        for (int k = 0; k < 4; k++) {
            const int g = l * NQ + 1 + k;
            float2 u0 = U[g][0];
            float2 u1 = U[g][1];
            const float s = sgn[k];
            u0.y *= s; u1.x *= s;
            const int m = 16 >> k;
            float2 b0v, b1v;
            b0v.x = __shfl_xor_sync(0xffffffffu, a0.x, m);
            b0v.y = __shfl_xor_sync(0xffffffffu, a0.y, m);
            b1v.x = __shfl_xor_sync(0xffffffffu, a1.x, m);
            b1v.y = __shfl_xor_sync(0xffffffffu, a1.y, m);
            a0 = cfma2(u0, a0, u1, b0v);
            a1 = cfma2(u0, a1, u1, b1v);
        }
        // CNOT ring + transpose back
        st[cur][SIDX(iB)]       = a0;
        st[cur][SIDX(iB + 512)] = a1;
        __syncthreads();
        a0 = st[cur][SIDX(Ct0)];
        a1 = st[cur][SIDX(Ct1)];
        cur ^= 1;
    }

    // <Z_q>
    const float p0 = fmaf(a0.x, a0.x, a0.y * a0.y);
    const float p1 = fmaf(a1.x, a1.x, a1.y * a1.y);
    #pragma unroll
    for (int q = 0; q < NQ; q++) {
        float v;
        if (q == 0) {
            v = p1;
        } else {
            const int mask = 1 << (NQ - 1 - q);
            v = (t & mask) ? (p0 + p1) : 0.0f;
        }
        #pragma unroll
        for (int o = 16; o > 0; o >>= 1) v += __shfl_xor_sync(0xffffffffu, v, o);
        if (lane == 0) wsum[warp][q] = v;
    }
    __syncthreads();
    if (t < NQ) {
        float s = 0.0f;
        #pragma unroll
        for (int w = 0; w < 16; w++) s += wsum[w][t];
        g_z[t] = 1.0f - 2.0f * s;
    }
    __syncthreads();
    if (t == 0) {
        __threadfence();
        atomicMax(&g_zflag, target);   // release; monotonic
    }
}

// ---------------------------------------------------------------------------
// Kernel C: broadcast fill — 64MB of float4 stores (the HBM floor).
// ---------------------------------------------------------------------------
__global__ void __launch_bounds__(256)
fill_kernel(float4* __restrict__ out) {
    const int col = threadIdx.x;
    const float4 v = ((const float4*)g_y)[col];
    const size_t base = (size_t)blockIdx.x * 4;
    #pragma unroll
    for (int r = 0; r < 4; r++) {
        out[(base + r) * (EDIM / 4) + col] = v;
    }
}

// ---------------------------------------------------------------------------
// inputs: 0=x, 1=W_in, 2=b_in, 3=params, 4=W1, 5=b1, 6=W2, 7=b2
// x / W_in / b_in are dead in the reference.
// ---------------------------------------------------------------------------
extern "C" void kernel_launch(void* const* d_in, const int* in_sizes, int n_in,
                              void* d_out, int out_size) {
    const float* params = (const float*)d_in[3];
    const float* W1     = (const float*)d_in[4];
    const float* b1     = (const float*)d_in[5];
    const float* W2     = (const float*)d_in[6];
    const float* b2     = (const float*)d_in[7];
    float* out = (float*)d_out;

    circuit_h_y_kernel<<<GRID_A, 512>>>(params, W1, b1, W2, b2);
    fill_kernel<<<NTOK / 4, 256>>>((float4*)out);
}